// round 3
// baseline (speedup 1.0000x reference)
#include <cuda_runtime.h>

#define B_ 8
#define L_ 2048
#define DM 6
#define ED 48
#define NS 32
#define DCONV 16
#define NL 4
#define NC 4
#define EPSv 1e-5f

#define FR 64                 // rows per frontend block
#define NCHUNK 64             // scan chunks
#define CL (L_/NCHUNK)        // 32 steps per chunk

// ---------------- scratch (device globals; no allocation) ----------------
__device__ float g_h[2][B_*L_*DM];
__device__ float g_y [B_*L_*ED];
__device__ float g_z [B_*L_*ED];
__device__ float g_xc[B_*L_*ED];
__device__ float g_dl[B_*L_*ED];
__device__ float g_Bm[B_*L_*NS];
__device__ float g_Cm[B_*L_*NS];
__device__ float g_pA[B_*NCHUNK*ED*NS];
__device__ float g_he[B_*NCHUNK*ED*NS];
__device__ float g_hi[B_*NCHUNK*ED*NS];
__device__ float g_hf[B_*ED*NS];

__device__ __forceinline__ float siluf(float v){ return __fdividef(v, 1.f + __expf(-v)); }
__device__ __forceinline__ float softplusf(float v){ return v > 20.f ? v : log1pf(__expf(v)); }

// ---------------- frontend: residual+norm+in_proj+conv+x_proj+delta ------
__global__ void k_front(const float* __restrict__ x,
                        const float* __restrict__ in_w,   // [2*ED, DM]
                        const float* __restrict__ cw,     // [ED, DCONV]
                        const float* __restrict__ cb,     // [ED]
                        const float* __restrict__ xpw,    // [1+2N, ED]
                        const float* __restrict__ dtw,    // [ED]
                        const float* __restrict__ dtb,    // [ED]
                        const float* __restrict__ nw,     // [DM]
                        const float* __restrict__ ow_prev,// [DM, ED] (layer-1)
                        int layer)
{
  __shared__ float s_xin[FR+DCONV-1][ED+1];
  __shared__ float s_xc [FR][ED+1];
  __shared__ float s_dr [FR];

  const int blk = blockIdx.x;
  const int b  = blk / (L_/FR);
  const int r0 = (blk % (L_/FR)) * FR;
  const int rd = (layer-1)&1, wr = layer&1;

  // Phase A: h (residual), rmsnorm, in_proj -> x_in (smem, incl. halo), z (global)
  for (int idx = threadIdx.x; idx < FR+DCONV-1; idx += blockDim.x){
    int row = r0 - (DCONV-1) + idx;
    if (row < 0){
      for (int e=0;e<ED;e++) s_xin[idx][e]=0.f;
      continue;
    }
    float h[DM];
    if (layer == 0){
      #pragma unroll
      for (int d=0; d<DM; d++) h[d] = x[(b*L_+row)*DM+d];
    } else {
      #pragma unroll
      for (int d=0; d<DM; d++) h[d] = g_h[rd][(b*L_+row)*DM+d];
      const float* yp = &g_y[(b*L_+row)*ED];
      for (int e=0;e<ED;e++){
        float ye = yp[e];
        #pragma unroll
        for (int d=0; d<DM; d++) h[d] += ow_prev[d*ED+e]*ye;
      }
    }
    if (idx >= DCONV-1){           // owned row -> persist residual stream
      #pragma unroll
      for (int d=0; d<DM; d++) g_h[wr][(b*L_+row)*DM+d] = h[d];
    }
    float ms = 0.f;
    #pragma unroll
    for (int d=0; d<DM; d++) ms += h[d]*h[d];
    float inv = rsqrtf(ms*(1.f/DM) + EPSv);
    float xn[DM];
    #pragma unroll
    for (int d=0; d<DM; d++) xn[d] = h[d]*inv*nw[d];
    for (int j=0; j<2*ED; j++){
      float acc = 0.f;
      #pragma unroll
      for (int d=0; d<DM; d++) acc += in_w[j*DM+d]*xn[d];
      if (j < ED)                s_xin[idx][j] = acc;
      else if (idx >= DCONV-1)   g_z[(b*L_+row)*ED + (j-ED)] = acc;
    }
  }
  __syncthreads();

  // Phase B1: depthwise causal conv + silu
  for (int job = threadIdx.x; job < FR*ED; job += blockDim.x){
    int rr = job/ED, e = job%ED;
    float acc = cb[e];
    #pragma unroll
    for (int k=0;k<DCONV;k++) acc += s_xin[rr+k][e]*cw[e*DCONV+k];
    float v = siluf(acc);
    s_xc[rr][e] = v;
    g_xc[(b*L_+r0+rr)*ED + e] = v;
  }
  __syncthreads();

  // Phase B2: x_proj -> dr, B, C
  for (int job = threadIdx.x; job < FR*(1+2*NS); job += blockDim.x){
    int rr = job/(1+2*NS), o = job%(1+2*NS);
    float acc = 0.f;
    for (int e=0;e<ED;e++) acc += xpw[o*ED+e]*s_xc[rr][e];
    int row = r0+rr;
    if (o == 0)            s_dr[rr] = acc;
    else if (o < 1+NS)     g_Bm[(b*L_+row)*NS + (o-1)]    = acc;
    else                   g_Cm[(b*L_+row)*NS + (o-1-NS)] = acc;
  }
  __syncthreads();

  // Phase B3: delta = softplus(dr*dtw + dtb)
  for (int job = threadIdx.x; job < FR*ED; job += blockDim.x){
    int rr = job/ED, e = job%ED;
    g_dl[(b*L_+r0+rr)*ED+e] = softplusf(s_dr[rr]*dtw[e] + dtb[e]);
  }
}

// ---------------- scan pass 1: per-chunk local scan from 0 ----------------
__global__ void k_scan1(const float* __restrict__ alog)
{
  const int b = blockIdx.x / NCHUNK, c = blockIdx.x % NCHUNK;
  const int n = threadIdx.x, ey = threadIdx.y;
  float a[3], h[3] = {0,0,0}, p[3] = {1,1,1};
  #pragma unroll
  for (int j=0;j<3;j++) a[j] = -__expf(alog[(ey+16*j)*NS+n]);
  const int t0 = c*CL;
  for (int t=t0; t<t0+CL; t++){
    int base = b*L_+t;
    float Bn = g_Bm[base*NS+n];
    #pragma unroll
    for (int j=0;j<3;j++){
      int e = ey+16*j;
      float d  = g_dl[base*ED+e];
      float xc = g_xc[base*ED+e];
      float dA = __expf(d*a[j]);
      h[j] = dA*h[j] + d*xc*Bn;
      p[j] *= dA;
    }
  }
  #pragma unroll
  for (int j=0;j<3;j++){
    int e = ey+16*j;
    int idx = ((b*NCHUNK+c)*ED+e)*NS+n;
    g_pA[idx] = p[j];
    g_he[idx] = h[j];
  }
}

// ---------------- scan pass 2: inter-chunk scan (tiny) --------------------
__global__ void k_scan2()
{
  int tid = blockIdx.x*blockDim.x + threadIdx.x;
  if (tid >= B_*ED*NS) return;
  int b = tid/(ED*NS);
  int r = tid%(ED*NS);
  float hin = 0.f;
  for (int c=0;c<NCHUNK;c++){
    int idx = (b*NCHUNK+c)*ED*NS + r;
    g_hi[idx] = hin;
    hin = g_pA[idx]*hin + g_he[idx];
  }
  g_hf[tid] = hin;   // full-sequence final state (used by last layer)
}

// ---------------- scan pass 3: re-run with h_in, emit gated y -------------
__global__ void k_scan3(const float* __restrict__ alog, const float* __restrict__ Dp)
{
  const int b = blockIdx.x / NCHUNK, c = blockIdx.x % NCHUNK;
  const int n = threadIdx.x, ey = threadIdx.y;
  float a[3], h[3], Dv[3];
  #pragma unroll
  for (int j=0;j<3;j++){
    int e = ey+16*j;
    a[j]  = -__expf(alog[e*NS+n]);
    h[j]  = g_hi[((b*NCHUNK+c)*ED+e)*NS+n];
    Dv[j] = Dp[e];
  }
  const int t0 = c*CL;
  for (int t=t0; t<t0+CL; t++){
    int base = b*L_+t;
    float Bn = g_Bm[base*NS+n];
    float Cn = g_Cm[base*NS+n];
    float y[3], xc3[3];
    #pragma unroll
    for (int j=0;j<3;j++){
      int e = ey+16*j;
      float d  = g_dl[base*ED+e];
      float xc = g_xc[base*ED+e];
      float dA = __expf(d*a[j]);
      h[j] = dA*h[j] + d*xc*Bn;
      y[j] = h[j]*Cn;
      xc3[j] = xc;
    }
    #pragma unroll
    for (int off=16; off>0; off>>=1){
      y[0] += __shfl_xor_sync(0xffffffffu, y[0], off);
      y[1] += __shfl_xor_sync(0xffffffffu, y[1], off);
      y[2] += __shfl_xor_sync(0xffffffffu, y[2], off);
    }
    if (n == 0){
      #pragma unroll
      for (int j=0;j<3;j++){
        int e = ey+16*j;
        float z = g_z[base*ED+e];
        g_y[base*ED+e] = (y[j] + Dv[j]*xc3[j]) * siluf(z);
      }
    }
  }
}

// ---------------- final: last-step y of layer 3 + FC head -----------------
__global__ void k_final(const float* __restrict__ Dp,
                        const float* __restrict__ fcw, const float* __restrict__ fcb,
                        float* __restrict__ out)
{
  __shared__ float s_y[ED];
  const int b = blockIdx.x;
  const int n = threadIdx.x, ey = threadIdx.y;
  const int base = b*L_ + (L_-1);
  float y[3];
  #pragma unroll
  for (int j=0;j<3;j++){
    int e = ey+16*j;
    y[j] = g_hf[(b*ED+e)*NS+n] * g_Cm[base*NS+n];
  }
  #pragma unroll
  for (int off=16; off>0; off>>=1){
    y[0] += __shfl_xor_sync(0xffffffffu, y[0], off);
    y[1] += __shfl_xor_sync(0xffffffffu, y[1], off);
    y[2] += __shfl_xor_sync(0xffffffffu, y[2], off);
  }
  if (n == 0){
    #pragma unroll
    for (int j=0;j<3;j++){
      int e = ey+16*j;
      float v = y[j] + Dp[e]*g_xc[base*ED+e];
      s_y[e] = v * siluf(g_z[base*ED+e]);
    }
  }
  __syncthreads();
  int tid = ey*32+n;
  if (tid < NC){
    float acc = fcb[tid];
    for (int e=0;e<ED;e++) acc += fcw[tid*ED+e]*s_y[e];
    out[b*NC+tid] = acc;
  }
}

// ---------------- launch ---------------------------------------------------
extern "C" void kernel_launch(void* const* d_in, const int* in_sizes, int n_in,
                              void* d_out, int out_size)
{
  const float* x    = (const float*)d_in[0];
  const float* inw  = (const float*)d_in[1];
  const float* cw   = (const float*)d_in[2];
  const float* cb   = (const float*)d_in[3];
  const float* xpw  = (const float*)d_in[4];
  const float* dtw  = (const float*)d_in[5];
  const float* dtb  = (const float*)d_in[6];
  const float* alog = (const float*)d_in[7];
  const float* Dp   = (const float*)d_in[8];
  const float* ow   = (const float*)d_in[9];
  const float* nw   = (const float*)d_in[10];
  const float* fcw  = (const float*)d_in[11];
  const float* fcb  = (const float*)d_in[12];
  float* out = (float*)d_out;

  dim3 sblk(32,16);
  for (int i=0; i<NL; i++){
    k_front<<<B_*(L_/FR), 256>>>(x,
                                 inw + i*2*ED*DM,
                                 cw  + i*ED*DCONV,
                                 cb  + i*ED,
                                 xpw + i*(1+2*NS)*ED,
                                 dtw + i*ED,
                                 dtb + i*ED,
                                 nw  + i*DM,
                                 (i ? ow + (i-1)*DM*ED : ow),
                                 i);
    k_scan1<<<B_*NCHUNK, sblk>>>(alog + i*ED*NS);
    k_scan2<<<(B_*ED*NS+255)/256, 256>>>();
    if (i < NL-1)
      k_scan3<<<B_*NCHUNK, sblk>>>(alog + i*ED*NS, Dp + i*ED);
  }
  k_final<<<B_, sblk>>>(Dp + (NL-1)*ED, fcw, fcb, out);
}

// round 4
// speedup vs baseline: 1.0001x; 1.0001x over previous
#include <cuda_runtime.h>

#define B_ 8
#define L_ 2048
#define DM 6
#define ED 48
#define NS 32
#define DCONV 16
#define NL 4
#define NC 4
#define EPSv 1e-5f

#define FR 64                 // rows per frontend block
#define NCHUNK 64             // scan chunks
#define CL (L_/NCHUNK)        // 32 steps per chunk

// ---------------- scratch (device globals; no allocation) ----------------
__device__ float g_h[2][B_*L_*DM];
__device__ float g_y [B_*L_*ED];
__device__ float g_z [B_*L_*ED];
__device__ float g_xc[B_*L_*ED];
__device__ float g_dl[B_*L_*ED];
__device__ float g_Bm[B_*L_*NS];
__device__ float g_Cm[B_*L_*NS];
__device__ float g_pA[B_*NCHUNK*ED*NS];
__device__ float g_he[B_*NCHUNK*ED*NS];
__device__ float g_hi[B_*NCHUNK*ED*NS];
__device__ float g_hf[B_*ED*NS];

__device__ __forceinline__ float siluf(float v){ return __fdividef(v, 1.f + __expf(-v)); }
__device__ __forceinline__ float softplusf(float v){ return v > 20.f ? v : log1pf(__expf(v)); }

// ---------------- frontend: residual+norm+in_proj+conv+x_proj+delta ------
__global__ void k_front(const float* __restrict__ x,
                        const float* __restrict__ in_w,   // [2*ED, DM]
                        const float* __restrict__ cw,     // [ED, DCONV]
                        const float* __restrict__ cb,     // [ED]
                        const float* __restrict__ xpw,    // [1+2N, ED]
                        const float* __restrict__ dtw,    // [ED]
                        const float* __restrict__ dtb,    // [ED]
                        const float* __restrict__ nw,     // [DM]
                        const float* __restrict__ ow_prev,// [DM, ED] (layer-1)
                        int layer)
{
  __shared__ float s_xin[FR+DCONV-1][ED+1];
  __shared__ float s_xc [FR][ED+1];
  __shared__ float s_dr [FR];

  const int blk = blockIdx.x;
  const int b  = blk / (L_/FR);
  const int r0 = (blk % (L_/FR)) * FR;
  const int rd = (layer-1)&1, wr = layer&1;

  // Phase A: h (residual), rmsnorm, in_proj -> x_in (smem, incl. halo), z (global)
  for (int idx = threadIdx.x; idx < FR+DCONV-1; idx += blockDim.x){
    int row = r0 - (DCONV-1) + idx;
    if (row < 0){
      for (int e=0;e<ED;e++) s_xin[idx][e]=0.f;
      continue;
    }
    float h[DM];
    if (layer == 0){
      #pragma unroll
      for (int d=0; d<DM; d++) h[d] = x[(b*L_+row)*DM+d];
    } else {
      #pragma unroll
      for (int d=0; d<DM; d++) h[d] = g_h[rd][(b*L_+row)*DM+d];
      const float* yp = &g_y[(b*L_+row)*ED];
      for (int e=0;e<ED;e++){
        float ye = yp[e];
        #pragma unroll
        for (int d=0; d<DM; d++) h[d] += ow_prev[d*ED+e]*ye;
      }
    }
    if (idx >= DCONV-1){           // owned row -> persist residual stream
      #pragma unroll
      for (int d=0; d<DM; d++) g_h[wr][(b*L_+row)*DM+d] = h[d];
    }
    float ms = 0.f;
    #pragma unroll
    for (int d=0; d<DM; d++) ms += h[d]*h[d];
    float inv = rsqrtf(ms*(1.f/DM) + EPSv);
    float xn[DM];
    #pragma unroll
    for (int d=0; d<DM; d++) xn[d] = h[d]*inv*nw[d];
    for (int j=0; j<2*ED; j++){
      float acc = 0.f;
      #pragma unroll
      for (int d=0; d<DM; d++) acc += in_w[j*DM+d]*xn[d];
      if (j < ED)                s_xin[idx][j] = acc;
      else if (idx >= DCONV-1)   g_z[(b*L_+row)*ED + (j-ED)] = acc;
    }
  }
  __syncthreads();

  // Phase B1: depthwise causal conv + silu
  for (int job = threadIdx.x; job < FR*ED; job += blockDim.x){
    int rr = job/ED, e = job%ED;
    float acc = cb[e];
    #pragma unroll
    for (int k=0;k<DCONV;k++) acc += s_xin[rr+k][e]*cw[e*DCONV+k];
    float v = siluf(acc);
    s_xc[rr][e] = v;
    g_xc[(b*L_+r0+rr)*ED + e] = v;
  }
  __syncthreads();

  // Phase B2: x_proj -> dr, B, C
  for (int job = threadIdx.x; job < FR*(1+2*NS); job += blockDim.x){
    int rr = job/(1+2*NS), o = job%(1+2*NS);
    float acc = 0.f;
    for (int e=0;e<ED;e++) acc += xpw[o*ED+e]*s_xc[rr][e];
    int row = r0+rr;
    if (o == 0)            s_dr[rr] = acc;
    else if (o < 1+NS)     g_Bm[(b*L_+row)*NS + (o-1)]    = acc;
    else                   g_Cm[(b*L_+row)*NS + (o-1-NS)] = acc;
  }
  __syncthreads();

  // Phase B3: delta = softplus(dr*dtw + dtb)
  for (int job = threadIdx.x; job < FR*ED; job += blockDim.x){
    int rr = job/ED, e = job%ED;
    g_dl[(b*L_+r0+rr)*ED+e] = softplusf(s_dr[rr]*dtw[e] + dtb[e]);
  }
}

// ---------------- scan pass 1: per-chunk local scan from 0 ----------------
__global__ void k_scan1(const float* __restrict__ alog)
{
  const int b = blockIdx.x / NCHUNK, c = blockIdx.x % NCHUNK;
  const int n = threadIdx.x, ey = threadIdx.y;
  float a[3], h[3] = {0,0,0}, p[3] = {1,1,1};
  #pragma unroll
  for (int j=0;j<3;j++) a[j] = -__expf(alog[(ey+16*j)*NS+n]);
  const int t0 = c*CL;
  for (int t=t0; t<t0+CL; t++){
    int base = b*L_+t;
    float Bn = g_Bm[base*NS+n];
    #pragma unroll
    for (int j=0;j<3;j++){
      int e = ey+16*j;
      float d  = g_dl[base*ED+e];
      float xc = g_xc[base*ED+e];
      float dA = __expf(d*a[j]);
      h[j] = dA*h[j] + d*xc*Bn;
      p[j] *= dA;
    }
  }
  #pragma unroll
  for (int j=0;j<3;j++){
    int e = ey+16*j;
    int idx = ((b*NCHUNK+c)*ED+e)*NS+n;
    g_pA[idx] = p[j];
    g_he[idx] = h[j];
  }
}

// ---------------- scan pass 2: inter-chunk scan (tiny) --------------------
__global__ void k_scan2()
{
  int tid = blockIdx.x*blockDim.x + threadIdx.x;
  if (tid >= B_*ED*NS) return;
  int b = tid/(ED*NS);
  int r = tid%(ED*NS);
  float hin = 0.f;
  for (int c=0;c<NCHUNK;c++){
    int idx = (b*NCHUNK+c)*ED*NS + r;
    g_hi[idx] = hin;
    hin = g_pA[idx]*hin + g_he[idx];
  }
  g_hf[tid] = hin;   // full-sequence final state (used by last layer)
}

// ---------------- scan pass 3: re-run with h_in, emit gated y -------------
__global__ void k_scan3(const float* __restrict__ alog, const float* __restrict__ Dp)
{
  const int b = blockIdx.x / NCHUNK, c = blockIdx.x % NCHUNK;
  const int n = threadIdx.x, ey = threadIdx.y;
  float a[3], h[3], Dv[3];
  #pragma unroll
  for (int j=0;j<3;j++){
    int e = ey+16*j;
    a[j]  = -__expf(alog[e*NS+n]);
    h[j]  = g_hi[((b*NCHUNK+c)*ED+e)*NS+n];
    Dv[j] = Dp[e];
  }
  const int t0 = c*CL;
  for (int t=t0; t<t0+CL; t++){
    int base = b*L_+t;
    float Bn = g_Bm[base*NS+n];
    float Cn = g_Cm[base*NS+n];
    float y[3], xc3[3];
    #pragma unroll
    for (int j=0;j<3;j++){
      int e = ey+16*j;
      float d  = g_dl[base*ED+e];
      float xc = g_xc[base*ED+e];
      float dA = __expf(d*a[j]);
      h[j] = dA*h[j] + d*xc*Bn;
      y[j] = h[j]*Cn;
      xc3[j] = xc;
    }
    #pragma unroll
    for (int off=16; off>0; off>>=1){
      y[0] += __shfl_xor_sync(0xffffffffu, y[0], off);
      y[1] += __shfl_xor_sync(0xffffffffu, y[1], off);
      y[2] += __shfl_xor_sync(0xffffffffu, y[2], off);
    }
    if (n == 0){
      #pragma unroll
      for (int j=0;j<3;j++){
        int e = ey+16*j;
        float z = g_z[base*ED+e];
        g_y[base*ED+e] = (y[j] + Dv[j]*xc3[j]) * siluf(z);
      }
    }
  }
}

// ---------------- final: last-step y of layer 3 + FC head -----------------
__global__ void k_final(const float* __restrict__ Dp,
                        const float* __restrict__ fcw, const float* __restrict__ fcb,
                        float* __restrict__ out)
{
  __shared__ float s_y[ED];
  const int b = blockIdx.x;
  const int n = threadIdx.x, ey = threadIdx.y;
  const int base = b*L_ + (L_-1);
  float y[3];
  #pragma unroll
  for (int j=0;j<3;j++){
    int e = ey+16*j;
    y[j] = g_hf[(b*ED+e)*NS+n] * g_Cm[base*NS+n];
  }
  #pragma unroll
  for (int off=16; off>0; off>>=1){
    y[0] += __shfl_xor_sync(0xffffffffu, y[0], off);
    y[1] += __shfl_xor_sync(0xffffffffu, y[1], off);
    y[2] += __shfl_xor_sync(0xffffffffu, y[2], off);
  }
  if (n == 0){
    #pragma unroll
    for (int j=0;j<3;j++){
      int e = ey+16*j;
      float v = y[j] + Dp[e]*g_xc[base*ED+e];
      s_y[e] = v * siluf(g_z[base*ED+e]);
    }
  }
  __syncthreads();
  int tid = ey*32+n;
  if (tid < NC){
    float acc = fcb[tid];
    for (int e=0;e<ED;e++) acc += fcw[tid*ED+e]*s_y[e];
    out[b*NC+tid] = acc;
  }
}

// ---------------- launch ---------------------------------------------------
extern "C" void kernel_launch(void* const* d_in, const int* in_sizes, int n_in,
                              void* d_out, int out_size)
{
  const float* x    = (const float*)d_in[0];
  const float* inw  = (const float*)d_in[1];
  const float* cw   = (const float*)d_in[2];
  const float* cb   = (const float*)d_in[3];
  const float* xpw  = (const float*)d_in[4];
  const float* dtw  = (const float*)d_in[5];
  const float* dtb  = (const float*)d_in[6];
  const float* alog = (const float*)d_in[7];
  const float* Dp   = (const float*)d_in[8];
  const float* ow   = (const float*)d_in[9];
  const float* nw   = (const float*)d_in[10];
  const float* fcw  = (const float*)d_in[11];
  const float* fcb  = (const float*)d_in[12];
  float* out = (float*)d_out;

  dim3 sblk(32,16);
  for (int i=0; i<NL; i++){
    k_front<<<B_*(L_/FR), 256>>>(x,
                                 inw + i*2*ED*DM,
                                 cw  + i*ED*DCONV,
                                 cb  + i*ED,
                                 xpw + i*(1+2*NS)*ED,
                                 dtw + i*ED,
                                 dtb + i*ED,
                                 nw  + i*DM,
                                 (i ? ow + (i-1)*DM*ED : ow),
                                 i);
    k_scan1<<<B_*NCHUNK, sblk>>>(alog + i*ED*NS);
    k_scan2<<<(B_*ED*NS+255)/256, 256>>>();
    if (i < NL-1)
      k_scan3<<<B_*NCHUNK, sblk>>>(alog + i*ED*NS, Dp + i*ED);
  }
  k_final<<<B_, sblk>>>(Dp + (NL-1)*ED, fcw, fcb, out);
}

// round 5
// speedup vs baseline: 1.0080x; 1.0079x over previous
#include <cuda_runtime.h>

#define B_ 8
#define L_ 2048
#define DM 6
#define ED 48
#define NS 32
#define DCONV 16
#define NL 4
#define NC 4
#define EPSv 1e-5f

#define FR 64                 // rows per frontend block
#define NCHUNK 64             // scan chunks
#define CL (L_/NCHUNK)        // 32 steps per chunk

// ---------------- scratch (device globals; no allocation) ----------------
__device__ float g_h[2][B_*L_*DM];
__device__ float g_y [B_*L_*ED];
__device__ float g_z [B_*L_*ED];
__device__ float g_xc[B_*L_*ED];
__device__ float g_dl[B_*L_*ED];
__device__ float g_Bm[B_*L_*NS];
__device__ float g_Cm[B_*L_*NS];
__device__ float g_pA[B_*NCHUNK*ED*NS];
__device__ float g_he[B_*NCHUNK*ED*NS];
__device__ float g_hi[B_*NCHUNK*ED*NS];
__device__ float g_hf[B_*ED*NS];

__device__ __forceinline__ float siluf(float v){ return __fdividef(v, 1.f + __expf(-v)); }
__device__ __forceinline__ float softplusf(float v){ return v > 20.f ? v : log1pf(__expf(v)); }

// ---------------- frontend: residual+norm+in_proj+conv+x_proj+delta ------
__global__ void k_front(const float* __restrict__ x,
                        const float* __restrict__ in_w,   // [2*ED, DM]
                        const float* __restrict__ cw,     // [ED, DCONV]
                        const float* __restrict__ cb,     // [ED]
                        const float* __restrict__ xpw,    // [1+2N, ED]
                        const float* __restrict__ dtw,    // [ED]
                        const float* __restrict__ dtb,    // [ED]
                        const float* __restrict__ nw,     // [DM]
                        const float* __restrict__ ow_prev,// [DM, ED] (layer-1)
                        int layer)
{
  __shared__ float s_xin[FR+DCONV-1][ED+1];
  __shared__ float s_xc [FR][ED+1];
  __shared__ float s_dr [FR];

  const int blk = blockIdx.x;
  const int b  = blk / (L_/FR);
  const int r0 = (blk % (L_/FR)) * FR;
  const int rd = (layer-1)&1, wr = layer&1;

  // Phase A: h (residual), rmsnorm, in_proj -> x_in (smem, incl. halo), z (global)
  for (int idx = threadIdx.x; idx < FR+DCONV-1; idx += blockDim.x){
    int row = r0 - (DCONV-1) + idx;
    if (row < 0){
      for (int e=0;e<ED;e++) s_xin[idx][e]=0.f;
      continue;
    }
    float h[DM];
    if (layer == 0){
      #pragma unroll
      for (int d=0; d<DM; d++) h[d] = x[(b*L_+row)*DM+d];
    } else {
      #pragma unroll
      for (int d=0; d<DM; d++) h[d] = g_h[rd][(b*L_+row)*DM+d];
      const float* yp = &g_y[(b*L_+row)*ED];
      for (int e=0;e<ED;e++){
        float ye = yp[e];
        #pragma unroll
        for (int d=0; d<DM; d++) h[d] += ow_prev[d*ED+e]*ye;
      }
    }
    if (idx >= DCONV-1){           // owned row -> persist residual stream
      #pragma unroll
      for (int d=0; d<DM; d++) g_h[wr][(b*L_+row)*DM+d] = h[d];
    }
    float ms = 0.f;
    #pragma unroll
    for (int d=0; d<DM; d++) ms += h[d]*h[d];
    float inv = rsqrtf(ms*(1.f/DM) + EPSv);
    float xn[DM];
    #pragma unroll
    for (int d=0; d<DM; d++) xn[d] = h[d]*inv*nw[d];
    for (int j=0; j<2*ED; j++){
      float acc = 0.f;
      #pragma unroll
      for (int d=0; d<DM; d++) acc += in_w[j*DM+d]*xn[d];
      if (j < ED)                s_xin[idx][j] = acc;
      else if (idx >= DCONV-1)   g_z[(b*L_+row)*ED + (j-ED)] = acc;
    }
  }
  __syncthreads();

  // Phase B1: depthwise causal conv + silu
  for (int job = threadIdx.x; job < FR*ED; job += blockDim.x){
    int rr = job/ED, e = job%ED;
    float acc = cb[e];
    #pragma unroll
    for (int k=0;k<DCONV;k++) acc += s_xin[rr+k][e]*cw[e*DCONV+k];
    float v = siluf(acc);
    s_xc[rr][e] = v;
    g_xc[(b*L_+r0+rr)*ED + e] = v;
  }
  __syncthreads();

  // Phase B2: x_proj -> dr, B, C
  for (int job = threadIdx.x; job < FR*(1+2*NS); job += blockDim.x){
    int rr = job/(1+2*NS), o = job%(1+2*NS);
    float acc = 0.f;
    for (int e=0;e<ED;e++) acc += xpw[o*ED+e]*s_xc[rr][e];
    int row = r0+rr;
    if (o == 0)            s_dr[rr] = acc;
    else if (o < 1+NS)     g_Bm[(b*L_+row)*NS + (o-1)]    = acc;
    else                   g_Cm[(b*L_+row)*NS + (o-1-NS)] = acc;
  }
  __syncthreads();

  // Phase B3: delta = softplus(dr*dtw + dtb)
  for (int job = threadIdx.x; job < FR*ED; job += blockDim.x){
    int rr = job/ED, e = job%ED;
    g_dl[(b*L_+r0+rr)*ED+e] = softplusf(s_dr[rr]*dtw[e] + dtb[e]);
  }
}

// ---------------- scan pass 1: per-chunk local scan from 0 ----------------
__global__ void k_scan1(const float* __restrict__ alog)
{
  const int b = blockIdx.x / NCHUNK, c = blockIdx.x % NCHUNK;
  const int n = threadIdx.x, ey = threadIdx.y;
  float a[3], h[3] = {0,0,0}, p[3] = {1,1,1};
  #pragma unroll
  for (int j=0;j<3;j++) a[j] = -__expf(alog[(ey+16*j)*NS+n]);
  const int t0 = c*CL;
  for (int t=t0; t<t0+CL; t++){
    int base = b*L_+t;
    float Bn = g_Bm[base*NS+n];
    #pragma unroll
    for (int j=0;j<3;j++){
      int e = ey+16*j;
      float d  = g_dl[base*ED+e];
      float xc = g_xc[base*ED+e];
      float dA = __expf(d*a[j]);
      h[j] = dA*h[j] + d*xc*Bn;
      p[j] *= dA;
    }
  }
  #pragma unroll
  for (int j=0;j<3;j++){
    int e = ey+16*j;
    int idx = ((b*NCHUNK+c)*ED+e)*NS+n;
    g_pA[idx] = p[j];
    g_he[idx] = h[j];
  }
}

// ---------------- scan pass 2: inter-chunk scan (tiny) --------------------
__global__ void k_scan2()
{
  int tid = blockIdx.x*blockDim.x + threadIdx.x;
  if (tid >= B_*ED*NS) return;
  int b = tid/(ED*NS);
  int r = tid%(ED*NS);
  float hin = 0.f;
  for (int c=0;c<NCHUNK;c++){
    int idx = (b*NCHUNK+c)*ED*NS + r;
    g_hi[idx] = hin;
    hin = g_pA[idx]*hin + g_he[idx];
  }
  g_hf[tid] = hin;   // full-sequence final state (used by last layer)
}

// ---------------- scan pass 3: re-run with h_in, emit gated y -------------
__global__ void k_scan3(const float* __restrict__ alog, const float* __restrict__ Dp)
{
  const int b = blockIdx.x / NCHUNK, c = blockIdx.x % NCHUNK;
  const int n = threadIdx.x, ey = threadIdx.y;
  float a[3], h[3], Dv[3];
  #pragma unroll
  for (int j=0;j<3;j++){
    int e = ey+16*j;
    a[j]  = -__expf(alog[e*NS+n]);
    h[j]  = g_hi[((b*NCHUNK+c)*ED+e)*NS+n];
    Dv[j] = Dp[e];
  }
  const int t0 = c*CL;
  for (int t=t0; t<t0+CL; t++){
    int base = b*L_+t;
    float Bn = g_Bm[base*NS+n];
    float Cn = g_Cm[base*NS+n];
    float y[3], xc3[3];
    #pragma unroll
    for (int j=0;j<3;j++){
      int e = ey+16*j;
      float d  = g_dl[base*ED+e];
      float xc = g_xc[base*ED+e];
      float dA = __expf(d*a[j]);
      h[j] = dA*h[j] + d*xc*Bn;
      y[j] = h[j]*Cn;
      xc3[j] = xc;
    }
    #pragma unroll
    for (int off=16; off>0; off>>=1){
      y[0] += __shfl_xor_sync(0xffffffffu, y[0], off);
      y[1] += __shfl_xor_sync(0xffffffffu, y[1], off);
      y[2] += __shfl_xor_sync(0xffffffffu, y[2], off);
    }
    if (n == 0){
      #pragma unroll
      for (int j=0;j<3;j++){
        int e = ey+16*j;
        float z = g_z[base*ED+e];
        g_y[base*ED+e] = (y[j] + Dv[j]*xc3[j]) * siluf(z);
      }
    }
  }
}

// ---------------- final: last-step y of layer 3 + FC head -----------------
__global__ void k_final(const float* __restrict__ Dp,
                        const float* __restrict__ fcw, const float* __restrict__ fcb,
                        float* __restrict__ out)
{
  __shared__ float s_y[ED];
  const int b = blockIdx.x;
  const int n = threadIdx.x, ey = threadIdx.y;
  const int base = b*L_ + (L_-1);
  float y[3];
  #pragma unroll
  for (int j=0;j<3;j++){
    int e = ey+16*j;
    y[j] = g_hf[(b*ED+e)*NS+n] * g_Cm[base*NS+n];
  }
  #pragma unroll
  for (int off=16; off>0; off>>=1){
    y[0] += __shfl_xor_sync(0xffffffffu, y[0], off);
    y[1] += __shfl_xor_sync(0xffffffffu, y[1], off);
    y[2] += __shfl_xor_sync(0xffffffffu, y[2], off);
  }
  if (n == 0){
    #pragma unroll
    for (int j=0;j<3;j++){
      int e = ey+16*j;
      float v = y[j] + Dp[e]*g_xc[base*ED+e];
      s_y[e] = v * siluf(g_z[base*ED+e]);
    }
  }
  __syncthreads();
  int tid = ey*32+n;
  if (tid < NC){
    float acc = fcb[tid];
    for (int e=0;e<ED;e++) acc += fcw[tid*ED+e]*s_y[e];
    out[b*NC+tid] = acc;
  }
}

// ---------------- launch ---------------------------------------------------
extern "C" void kernel_launch(void* const* d_in, const int* in_sizes, int n_in,
                              void* d_out, int out_size)
{
  const float* x    = (const float*)d_in[0];
  const float* inw  = (const float*)d_in[1];
  const float* cw   = (const float*)d_in[2];
  const float* cb   = (const float*)d_in[3];
  const float* xpw  = (const float*)d_in[4];
  const float* dtw  = (const float*)d_in[5];
  const float* dtb  = (const float*)d_in[6];
  const float* alog = (const float*)d_in[7];
  const float* Dp   = (const float*)d_in[8];
  const float* ow   = (const float*)d_in[9];
  const float* nw   = (const float*)d_in[10];
  const float* fcw  = (const float*)d_in[11];
  const float* fcb  = (const float*)d_in[12];
  float* out = (float*)d_out;

  dim3 sblk(32,16);
  for (int i=0; i<NL; i++){
    k_front<<<B_*(L_/FR), 256>>>(x,
                                 inw + i*2*ED*DM,
                                 cw  + i*ED*DCONV,
                                 cb  + i*ED,
                                 xpw + i*(1+2*NS)*ED,
                                 dtw + i*ED,
                                 dtb + i*ED,
                                 nw  + i*DM,
                                 (i ? ow + (i-1)*DM*ED : ow),
                                 i);
    k_scan1<<<B_*NCHUNK, sblk>>>(alog + i*ED*NS);
    k_scan2<<<(B_*ED*NS+255)/256, 256>>>();
    if (i < NL-1)
      k_scan3<<<B_*NCHUNK, sblk>>>(alog + i*ED*NS, Dp + i*ED);
  }
  k_final<<<B_, sblk>>>(Dp + (NL-1)*ED, fcw, fcb, out);
}